// round 15
// baseline (speedup 1.0000x reference)
#include <cuda_runtime.h>
#include <cuda_bf16.h>
#include <math.h>
#include <stdint.h>

// ---------------------------------------------------------------------------
// Problem dims (fixed): a=b=8192, e1=e2=c=m=1024
constexpr int KDIM = 1024;
constexpr int A_MAX = 8192;

constexpr int BM = 128;
constexpr int BN = 128;
constexpr int KC = 64;                  // K chunk (bf16): 128 B per row
constexpr int NCHUNK = KDIM / KC;       // 16
constexpr int TILE_B = BM * 128;        // 16384 B per tile (128B rows)
constexpr int STAGE_B = 2 * TILE_B;     // A + B per stage = 32768
constexpr int NSTAGE = 3;
constexpr int SMEM_DYN = NSTAGE * STAGE_B;  // 98304 B per CTA (2 CTAs = 192KB)

constexpr int RPB = 16;                 // pool rows per block (compile-time)

// ---------------------------------------------------------------------------
// Device-global scratch
static __device__ __nv_bfloat16 g_x1[(size_t)A_MAX * KDIM];
static __device__ __nv_bfloat16 g_x2[(size_t)A_MAX * KDIM];
static __device__ __nv_bfloat16 g_wt1[(size_t)KDIM * KDIM];
static __device__ __nv_bfloat16 g_wt2[(size_t)KDIM * KDIM];
static __device__ __nv_bfloat16 g_p1[(size_t)A_MAX * KDIM];
static __device__ __nv_bfloat16 g_p2[(size_t)A_MAX * KDIM];
static __device__ float g_cvec[2 * KDIM];
static __device__ float g_s[2 * KDIM];
static __device__ float g_logits[2 * A_MAX];
static __device__ unsigned g_mx[2];      // ordered-key float max
static __device__ float g_sum[2];        // sum of exp(l - mx)

// ordered-uint key for float max atomics (monotone in x)
__device__ __forceinline__ unsigned fkey(float x) {
    unsigned u = __float_as_uint(x);
    return (u & 0x80000000u) ? ~u : (u | 0x80000000u);
}
__device__ __forceinline__ float fkey_inv(unsigned k) {
    return (k & 0x80000000u) ? __uint_as_float(k ^ 0x80000000u) : __uint_as_float(~k);
}
constexpr unsigned FKEY_NEG_MAX = 0x00800000u;   // fkey(-FLT_MAX)

// ---------------------------------------------------------------------------
__device__ __forceinline__ uint32_t smem_u32(const void* p) {
    uint32_t a;
    asm("{ .reg .u64 t; cvta.to.shared.u64 t, %1; cvt.u32.u64 %0, t; }" : "=r"(a) : "l"(p));
    return a;
}
__device__ __forceinline__ void cp16(uint32_t smem, const void* g) {
    asm volatile("cp.async.cg.shared.global [%0], [%1], 16;" :: "r"(smem), "l"(g) : "memory");
}
__device__ __forceinline__ void cp_commit() {
    asm volatile("cp.async.commit_group;" ::: "memory");
}
template <int N>
__device__ __forceinline__ void cp_wait() {
    asm volatile("cp.async.wait_group %0;" :: "n"(N) : "memory");
}
__device__ __forceinline__ void ldsm_x4(uint32_t addr, uint32_t* r) {
    asm volatile("ldmatrix.sync.aligned.m8n8.x4.shared.b16 {%0,%1,%2,%3}, [%4];"
                 : "=r"(r[0]), "=r"(r[1]), "=r"(r[2]), "=r"(r[3]) : "r"(addr));
}
__device__ __forceinline__ void mma16816(float* d, const uint32_t* a, const uint32_t* b) {
    asm volatile(
        "mma.sync.aligned.m16n8k16.row.col.f32.bf16.bf16.f32 "
        "{%0,%1,%2,%3}, {%4,%5,%6,%7}, {%8,%9}, {%0,%1,%2,%3};\n"
        : "+f"(d[0]), "+f"(d[1]), "+f"(d[2]), "+f"(d[3])
        : "r"(a[0]), "r"(a[1]), "r"(a[2]), "r"(a[3]), "r"(b[0]), "r"(b[1]));
}

// ---------------------------------------------------------------------------
// Fused prep: blocks [0, 256) do cvec (+ zero/init); blocks [256, ...) convert.
constexpr int NSEQ8 = A_MAX * KDIM / 8;
constexpr int NW8   = KDIM * KDIM / 8;
constexpr int NCONV = 2 * NSEQ8 + 2 * NW8;
constexpr int CVEC_BLOCKS = 256;
constexpr int CONV_BLOCKS = 2048;

__global__ void k_prep(const float4* __restrict__ s1, const float4* __restrict__ s2,
                       const float4* __restrict__ w1x, const float4* __restrict__ w2x,
                       const float* __restrict__ Wc1x, const float* __restrict__ Wc2x,
                       const float* __restrict__ b1x, const float* __restrict__ b2x,
                       const float* __restrict__ ctx,
                       float* __restrict__ out, int out_n) {
    const int bid = blockIdx.x;
    const int tid = threadIdx.x;

    if (bid < CVEC_BLOCKS) {
        if (bid == 0) {
            for (int i = tid; i < 2 * KDIM; i += 256) g_s[i] = 0.f;
            if (tid < 2) { g_mx[tid] = FKEY_NEG_MAX; g_sum[tid] = 0.f; }
        }
        if (bid == 1) { for (int i = tid; i < out_n; i += 256) out[i] = 0.f; }

        const int which = bid >> 7;
        const int blk   = bid & 127;
        const float* Wc = which ? Wc2x : Wc1x;
        const float* bias = which ? b2x : b1x;
        int warp = blk * 8 + (tid >> 5);
        int lane = tid & 31;
        const float4* wrow = (const float4*)(Wc + (size_t)warp * KDIM);
        const float4* c4   = (const float4*)ctx;
        float sum = 0.f;
#pragma unroll
        for (int it = 0; it < KDIM / 128; ++it) {
            float4 wv = wrow[lane + it * 32];
            float4 cv = c4[lane + it * 32];
            sum += wv.x * cv.x + wv.y * cv.y + wv.z * cv.z + wv.w * cv.w;
        }
#pragma unroll
        for (int o = 16; o; o >>= 1) sum += __shfl_xor_sync(0xffffffffu, sum, o);
        if (lane == 0) g_cvec[which * KDIM + warp] = sum + bias[warp];
        return;
    }

    // conversion: 4 units (32 elems, 128 B) per thread per step — high MLP
    const int stride = CONV_BLOCKS * 256;
    for (int u = (bid - CVEC_BLOCKS) * 256 + tid; u < NCONV / 4; u += stride) {
        int i = 4 * u;
        const float4* src;
        uint4* dst;
        int off;
        if (i < NSEQ8)                 { src = s1;  dst = (uint4*)g_x1;  off = i; }
        else if (i < 2 * NSEQ8)        { src = s2;  dst = (uint4*)g_x2;  off = i - NSEQ8; }
        else if (i < 2 * NSEQ8 + NW8)  { src = w1x; dst = (uint4*)g_wt1; off = i - 2 * NSEQ8; }
        else                           { src = w2x; dst = (uint4*)g_wt2; off = i - 2 * NSEQ8 - NW8; }
        float4 v[8];
#pragma unroll
        for (int j = 0; j < 8; ++j) v[j] = src[2 * off + j];
        uint4 o[4];
        __nv_bfloat162 t;
#pragma unroll
        for (int j = 0; j < 4; ++j) {
            t = __floats2bfloat162_rn(v[2*j].x, v[2*j].y);     o[j].x = *(uint32_t*)&t;
            t = __floats2bfloat162_rn(v[2*j].z, v[2*j].w);     o[j].y = *(uint32_t*)&t;
            t = __floats2bfloat162_rn(v[2*j+1].x, v[2*j+1].y); o[j].z = *(uint32_t*)&t;
            t = __floats2bfloat162_rn(v[2*j+1].z, v[2*j+1].w); o[j].w = *(uint32_t*)&t;
        }
#pragma unroll
        for (int j = 0; j < 4; ++j) dst[off + j] = o[j];
    }
}

// ---------------------------------------------------------------------------
// P = elu(X @ Wt.T + cvec). bf16 inputs, cp.async 3-stage pipeline,
// copy-before-MMA ordering. 256 threads = 8 warps (2x4, 64x32/warp), 2 CTAs/SM.
__global__ __launch_bounds__(256, 2)
void k_proj_mma() {
    extern __shared__ char dynsm[];
    const uint32_t sb = smem_u32(dynsm);

    const int which = blockIdx.z;
    const __nv_bfloat16* __restrict__ X  = which ? g_x2  : g_x1;
    const __nv_bfloat16* __restrict__ Wt = which ? g_wt2 : g_wt1;
    __nv_bfloat16* __restrict__ P = which ? g_p2 : g_p1;
    const float* __restrict__ cvec = g_cvec + which * KDIM;
    float* __restrict__ scol = g_s + which * KDIM;

    const int tid  = threadIdx.x;
    const int wid  = tid >> 5;
    const int lane = tid & 31;
    const int warpRow = wid & 1;
    const int warpCol = wid >> 1;
    const int rowBase = blockIdx.y * BM;
    const int colBase = blockIdx.x * BN;

    const int cprow = tid >> 3;
    const int cpcol = tid & 7;
    const uint32_t cpswz = (uint32_t)((cpcol ^ (cprow & 7)) << 4);
    const __nv_bfloat16* gA = X  + (size_t)(rowBase + cprow) * KDIM + cpcol * 8;
    const __nv_bfloat16* gB = Wt + (size_t)(colBase + cprow) * KDIM + cpcol * 8;

    const int laneQ = lane & 7;
    const int blkId = lane >> 3;
    const uint32_t aKc0 = (uint32_t)(blkId >> 1);
    const uint32_t bKc0 = (uint32_t)(blkId & 1);
    uint32_t aRowOff[4], bRowOff[2];
#pragma unroll
    for (int rb = 0; rb < 4; ++rb)
        aRowOff[rb] = (uint32_t)(warpRow * 64 + rb * 16 + (blkId & 1) * 8 + laneQ) * 128u;
#pragma unroll
    for (int pr = 0; pr < 2; ++pr)
        bRowOff[pr] = (uint32_t)(warpCol * 32 + pr * 16 + (blkId >> 1) * 8 + laneQ) * 128u;

    uint32_t aSwT[4], bSwT[4];
#pragma unroll
    for (int ks = 0; ks < 4; ++ks) {
        aSwT[ks] = (uint32_t)((((uint32_t)(ks * 2) + aKc0) ^ (uint32_t)laneQ) << 4);
        bSwT[ks] = (uint32_t)((((uint32_t)(ks * 2) + bKc0) ^ (uint32_t)laneQ) << 4);
    }

    float acc[4][4][4] = {};

    auto issue = [&](int s, int c) {
        const uint32_t stg = sb + (uint32_t)s * STAGE_B;
        const int ko = c * KC;
#pragma unroll
        for (int it = 0; it < 4; ++it) {
            uint32_t soff = (uint32_t)(cprow + 32 * it) * 128u + cpswz;
            cp16(stg + soff,          gA + (size_t)(32 * it) * KDIM + ko);
            cp16(stg + TILE_B + soff, gB + (size_t)(32 * it) * KDIM + ko);
        }
        cp_commit();
    };

    issue(0, 0);
    issue(1, 1);

    int stage = 0;
    int wstage = 2;
    for (int c = 0; c < NCHUNK; ++c) {
        if (c == NCHUNK - 1) cp_wait<0>(); else cp_wait<1>();
        __syncthreads();

        if (c + 2 < NCHUNK) {
            issue(wstage, c + 2);
            wstage = (wstage == 2) ? 0 : wstage + 1;
        }

        const uint32_t smA = sb + (uint32_t)stage * STAGE_B;
        const uint32_t smB = smA + TILE_B;
#pragma unroll
        for (int ks = 0; ks < 4; ++ks) {
            uint32_t af[4][4], bf[2][4];
#pragma unroll
            for (int rb = 0; rb < 4; ++rb)
                ldsm_x4(smA + aRowOff[rb] + aSwT[ks], af[rb]);
#pragma unroll
            for (int pr = 0; pr < 2; ++pr)
                ldsm_x4(smB + bRowOff[pr] + bSwT[ks], bf[pr]);
#pragma unroll
            for (int cf = 0; cf < 4; ++cf) {
                const uint32_t* bp = &bf[cf >> 1][(cf & 1) * 2];
#pragma unroll
                for (int rb = 0; rb < 4; ++rb)
                    mma16816(acc[rb][cf], af[rb], bp);
            }
        }

        stage = (stage == 2) ? 0 : stage + 1;
    }

    // ---- epilogue: +cvec, ELU, bf16 store, column sums ----
    const int gq  = lane >> 2;
    const int tig = lane & 3;
    float csum[8];
#pragma unroll
    for (int j = 0; j < 8; ++j) csum[j] = 0.f;

#pragma unroll
    for (int rb = 0; rb < 4; ++rb) {
#pragma unroll
        for (int cf = 0; cf < 4; ++cf) {
            const int col = colBase + warpCol * 32 + cf * 8 + tig * 2;
            const float cv0 = cvec[col], cv1 = cvec[col + 1];
#pragma unroll
            for (int half = 0; half < 2; ++half) {
                const int row = rowBase + warpRow * 64 + rb * 16 + gq + half * 8;
                float v0 = acc[rb][cf][half * 2 + 0] + cv0;
                float v1 = acc[rb][cf][half * 2 + 1] + cv1;
                v0 = (v0 > 0.f) ? v0 : expm1f(v0);
                v1 = (v1 > 0.f) ? v1 : expm1f(v1);
                __nv_bfloat162 pk = __floats2bfloat162_rn(v0, v1);
                *(__nv_bfloat162*)(P + (size_t)row * KDIM + col) = pk;
                csum[cf * 2 + 0] += v0;
                csum[cf * 2 + 1] += v1;
            }
        }
    }
#pragma unroll
    for (int j = 0; j < 8; ++j) {
        float v = csum[j];
        v += __shfl_xor_sync(0xffffffffu, v, 4);
        v += __shfl_xor_sync(0xffffffffu, v, 8);
        v += __shfl_xor_sync(0xffffffffu, v, 16);
        if (gq == 0) {
            int col = colBase + warpCol * 32 + (j >> 1) * 8 + tig * 2 + (j & 1);
            atomicAdd(&scol[col], v);
        }
    }
}

// ---------------------------------------------------------------------------
// logits: 2 rows per warp. Also merges block max into g_mx[z].
__global__ void k_matvec(int M) {
    __shared__ float smax[8];
    const int gw   = (blockIdx.x * blockDim.x + threadIdx.x) >> 5;
    const int wloc = threadIdx.x >> 5;
    const int lane = threadIdx.x & 31;
    const int z = blockIdx.y;
    const int r0 = gw * 2;
    const __nv_bfloat16* P = z ? g_p2 : g_p1;
    const uint4* pr0 = (const uint4*)(P + (size_t)r0 * KDIM);
    const uint4* pr1 = (const uint4*)(P + (size_t)(r0 + 1) * KDIM);
    const float4* s4 = (const float4*)(g_s + (1 - z) * KDIM);
    float sum0 = 0.f, sum1 = 0.f;
#pragma unroll
    for (int it = 0; it < KDIM / 256; ++it) {
        uint4 pa = pr0[lane + it * 32];
        uint4 pb = pr1[lane + it * 32];
        float4 sa = s4[(lane + it * 32) * 2 + 0];
        float4 sbv = s4[(lane + it * 32) * 2 + 1];
        float2 q;
        q = __bfloat1622float2(*(const __nv_bfloat162*)&pa.x); sum0 += q.x * sa.x + q.y * sa.y;
        q = __bfloat1622float2(*(const __nv_bfloat162*)&pa.y); sum0 += q.x * sa.z + q.y * sa.w;
        q = __bfloat1622float2(*(const __nv_bfloat162*)&pa.z); sum0 += q.x * sbv.x + q.y * sbv.y;
        q = __bfloat1622float2(*(const __nv_bfloat162*)&pa.w); sum0 += q.x * sbv.z + q.y * sbv.w;
        q = __bfloat1622float2(*(const __nv_bfloat162*)&pb.x); sum1 += q.x * sa.x + q.y * sa.y;
        q = __bfloat1622float2(*(const __nv_bfloat162*)&pb.y); sum1 += q.x * sa.z + q.y * sa.w;
        q = __bfloat1622float2(*(const __nv_bfloat162*)&pb.z); sum1 += q.x * sbv.x + q.y * sbv.y;
        q = __bfloat1622float2(*(const __nv_bfloat162*)&pb.w); sum1 += q.x * sbv.z + q.y * sbv.w;
    }
#pragma unroll
    for (int o = 16; o; o >>= 1) {
        sum0 += __shfl_xor_sync(0xffffffffu, sum0, o);
        sum1 += __shfl_xor_sync(0xffffffffu, sum1, o);
    }
    if (lane == 0) {
        g_logits[z * A_MAX + r0]     = sum0;
        g_logits[z * A_MAX + r0 + 1] = sum1;
        smax[wloc] = fmaxf(sum0, sum1);
    }
    __syncthreads();
    if (threadIdx.x == 0) {
        float m = smax[0];
#pragma unroll
        for (int i = 1; i < 8; ++i) m = fmaxf(m, smax[i]);
        atomicMax(&g_mx[z], fkey(m));
    }
}

// out[z*KDIM + col4] += sum_r e^{l_r - mx} * seq_z[r, col4] (UNNORMALIZED);
// RPB=16 compile-time rows, fully unrolled for MLP. Partial sums -> g_sum[z].
// All 32 lanes of warp 0 participate in the weight phase (lanes >= RPB
// contribute 0) so the full-mask shuffle is convergent.
__global__ void k_pool(const float* __restrict__ seq1, const float* __restrict__ seq2,
                       float* __restrict__ out) {
    __shared__ float wsh[RPB];
    const int z = blockIdx.z;
    const float* seq = z ? seq2 : seq1;
    const int c4 = threadIdx.x;
    const int r0 = blockIdx.y * RPB;
    if (threadIdx.x < 32) {
        float e = 0.f;
        if (threadIdx.x < RPB) {
            float mx = fkey_inv(g_mx[z]);
            e = expf(g_logits[z * A_MAX + r0 + threadIdx.x] - mx);
            wsh[threadIdx.x] = e;
        }
        float t = e;
#pragma unroll
        for (int o = 16; o; o >>= 1) t += __shfl_xor_sync(0xffffffffu, t, o);
        if (threadIdx.x == 0) atomicAdd(&g_sum[z], t);
    }
    __syncthreads();
    float4 acc = {0.f, 0.f, 0.f, 0.f};
#pragma unroll
    for (int r = 0; r < RPB; ++r) {
        float wr = wsh[r];
        float4 v = *(const float4*)(seq + (size_t)(r0 + r) * KDIM + c4 * 4);
        acc.x += wr * v.x; acc.y += wr * v.y; acc.z += wr * v.z; acc.w += wr * v.w;
    }
    float* o = out + z * KDIM + c4 * 4;
    atomicAdd(o + 0, acc.x);
    atomicAdd(o + 1, acc.y);
    atomicAdd(o + 2, acc.z);
    atomicAdd(o + 3, acc.w);
}

// out[i] /= g_sum[z]  (2048 elems)
__global__ void k_norm(float* __restrict__ out) {
    int i = blockIdx.x * blockDim.x + threadIdx.x;
    if (i < 2 * KDIM) out[i] *= (1.f / g_sum[i >> 10]);
}

// ---------------------------------------------------------------------------
extern "C" void kernel_launch(void* const* d_in, const int* in_sizes, int n_in,
                              void* d_out, int out_size) {
    const float* seq1 = (const float*)d_in[0];
    const float* seq2 = (const float*)d_in[1];
    const float* ctx  = (const float*)d_in[2];
    const float* Wc1  = (const float*)d_in[3];
    const float* W1   = (const float*)d_in[4];
    const float* b1   = (const float*)d_in[5];
    const float* Wc2  = (const float*)d_in[6];
    const float* W2   = (const float*)d_in[7];
    const float* b2   = (const float*)d_in[8];
    float* out = (float*)d_out;

    const int a = in_sizes[0] / KDIM;   // 8192
    const int b = in_sizes[1] / KDIM;   // 8192

    cudaFuncSetAttribute(k_proj_mma, cudaFuncAttributeMaxDynamicSharedMemorySize, SMEM_DYN);

    k_prep<<<CVEC_BLOCKS + CONV_BLOCKS, 256>>>(
        (const float4*)seq1, (const float4*)seq2, (const float4*)W1, (const float4*)W2,
        Wc1, Wc2, b1, b2, ctx, out, out_size);

    {
        dim3 g(KDIM / BN, a / BM, 2);
        k_proj_mma<<<g, 256, SMEM_DYN>>>();
    }

    {
        dim3 gm(a / 16, 2);
        k_matvec<<<gm, 256>>>(a);
    }

    {
        dim3 gp(1, a / RPB, 2);
        k_pool<<<gp, 256>>>(seq1, seq2, out);
    }

    k_norm<<<8, 256>>>(out);
}

// round 16
// speedup vs baseline: 1.1646x; 1.1646x over previous
#include <cuda_runtime.h>
#include <cuda_bf16.h>
#include <math.h>
#include <stdint.h>

// ---------------------------------------------------------------------------
// Problem dims (fixed): a=b=8192, e1=e2=c=m=1024
constexpr int KDIM = 1024;
constexpr int A_MAX = 8192;

constexpr int BM = 128;
constexpr int BN = 128;
constexpr int KC = 64;                  // K chunk (bf16): 128 B per row
constexpr int NCHUNK = KDIM / KC;       // 16
constexpr int TILE_B = BM * 128;        // 16384 B per tile (128B rows)
constexpr int STAGE_B = 2 * TILE_B;     // A + B per stage = 32768
constexpr int NSTAGE = 3;
constexpr int SMEM_DYN = NSTAGE * STAGE_B;  // 98304 B per CTA (2 CTAs = 192KB)

constexpr int RPB = 32;                 // pool rows per block (as R12)

// ---------------------------------------------------------------------------
// Device-global scratch
static __device__ __nv_bfloat16 g_x1[(size_t)A_MAX * KDIM];
static __device__ __nv_bfloat16 g_x2[(size_t)A_MAX * KDIM];
static __device__ __nv_bfloat16 g_wt1[(size_t)KDIM * KDIM];
static __device__ __nv_bfloat16 g_wt2[(size_t)KDIM * KDIM];
static __device__ __nv_bfloat16 g_p1[(size_t)A_MAX * KDIM];
static __device__ __nv_bfloat16 g_p2[(size_t)A_MAX * KDIM];
static __device__ float g_cvec[2 * KDIM];
static __device__ float g_s[2 * KDIM];
static __device__ float g_logits[2 * A_MAX];
static __device__ unsigned g_mx[2];      // ordered-key float max
static __device__ float g_sum[2];        // sum of exp(l - mx)

// ordered-uint key for float max atomics (monotone in x)
__device__ __forceinline__ unsigned fkey(float x) {
    unsigned u = __float_as_uint(x);
    return (u & 0x80000000u) ? ~u : (u | 0x80000000u);
}
__device__ __forceinline__ float fkey_inv(unsigned k) {
    return (k & 0x80000000u) ? __uint_as_float(k ^ 0x80000000u) : __uint_as_float(~k);
}
constexpr unsigned FKEY_NEG_MAX = 0x00800000u;   // fkey(-FLT_MAX)

// ---------------------------------------------------------------------------
__device__ __forceinline__ uint32_t smem_u32(const void* p) {
    uint32_t a;
    asm("{ .reg .u64 t; cvta.to.shared.u64 t, %1; cvt.u32.u64 %0, t; }" : "=r"(a) : "l"(p));
    return a;
}
__device__ __forceinline__ void cp16(uint32_t smem, const void* g) {
    asm volatile("cp.async.cg.shared.global [%0], [%1], 16;" :: "r"(smem), "l"(g) : "memory");
}
__device__ __forceinline__ void cp_commit() {
    asm volatile("cp.async.commit_group;" ::: "memory");
}
template <int N>
__device__ __forceinline__ void cp_wait() {
    asm volatile("cp.async.wait_group %0;" :: "n"(N) : "memory");
}
__device__ __forceinline__ void ldsm_x4(uint32_t addr, uint32_t* r) {
    asm volatile("ldmatrix.sync.aligned.m8n8.x4.shared.b16 {%0,%1,%2,%3}, [%4];"
                 : "=r"(r[0]), "=r"(r[1]), "=r"(r[2]), "=r"(r[3]) : "r"(addr));
}
__device__ __forceinline__ void mma16816(float* d, const uint32_t* a, const uint32_t* b) {
    asm volatile(
        "mma.sync.aligned.m16n8k16.row.col.f32.bf16.bf16.f32 "
        "{%0,%1,%2,%3}, {%4,%5,%6,%7}, {%8,%9}, {%0,%1,%2,%3};\n"
        : "+f"(d[0]), "+f"(d[1]), "+f"(d[2]), "+f"(d[3])
        : "r"(a[0]), "r"(a[1]), "r"(a[2]), "r"(a[3]), "r"(b[0]), "r"(b[1]));
}

// ---------------------------------------------------------------------------
// Fused prep: blocks [0, 256) do cvec (+ zero/init); blocks [256, ...) convert.
// (R12-proven 2-unit conversion.)
constexpr int NSEQ8 = A_MAX * KDIM / 8;
constexpr int NW8   = KDIM * KDIM / 8;
constexpr int NCONV = 2 * NSEQ8 + 2 * NW8;
constexpr int CVEC_BLOCKS = 256;
constexpr int CONV_BLOCKS = 2048;

__global__ void k_prep(const float4* __restrict__ s1, const float4* __restrict__ s2,
                       const float4* __restrict__ w1x, const float4* __restrict__ w2x,
                       const float* __restrict__ Wc1x, const float* __restrict__ Wc2x,
                       const float* __restrict__ b1x, const float* __restrict__ b2x,
                       const float* __restrict__ ctx,
                       float* __restrict__ out, int out_n) {
    const int bid = blockIdx.x;
    const int tid = threadIdx.x;

    if (bid < CVEC_BLOCKS) {
        if (bid == 0) {
            for (int i = tid; i < 2 * KDIM; i += 256) g_s[i] = 0.f;
            if (tid < 2) { g_mx[tid] = FKEY_NEG_MAX; g_sum[tid] = 0.f; }
        }
        if (bid == 1) { for (int i = tid; i < out_n; i += 256) out[i] = 0.f; }

        const int which = bid >> 7;
        const int blk   = bid & 127;
        const float* Wc = which ? Wc2x : Wc1x;
        const float* bias = which ? b2x : b1x;
        int warp = blk * 8 + (tid >> 5);
        int lane = tid & 31;
        const float4* wrow = (const float4*)(Wc + (size_t)warp * KDIM);
        const float4* c4   = (const float4*)ctx;
        float sum = 0.f;
#pragma unroll
        for (int it = 0; it < KDIM / 128; ++it) {
            float4 wv = wrow[lane + it * 32];
            float4 cv = c4[lane + it * 32];
            sum += wv.x * cv.x + wv.y * cv.y + wv.z * cv.z + wv.w * cv.w;
        }
#pragma unroll
        for (int o = 16; o; o >>= 1) sum += __shfl_xor_sync(0xffffffffu, sum, o);
        if (lane == 0) g_cvec[which * KDIM + warp] = sum + bias[warp];
        return;
    }

    // conversion: 2 units (16 elems) per thread per step (R12-proven)
    const int stride = CONV_BLOCKS * 256;
    for (int u = (bid - CVEC_BLOCKS) * 256 + tid; u < NCONV / 2; u += stride) {
        int i = 2 * u;
        const float4* src;
        uint4* dst;
        int off;
        if (i < NSEQ8)                 { src = s1;  dst = (uint4*)g_x1;  off = i; }
        else if (i < 2 * NSEQ8)        { src = s2;  dst = (uint4*)g_x2;  off = i - NSEQ8; }
        else if (i < 2 * NSEQ8 + NW8)  { src = w1x; dst = (uint4*)g_wt1; off = i - 2 * NSEQ8; }
        else                           { src = w2x; dst = (uint4*)g_wt2; off = i - 2 * NSEQ8 - NW8; }
        float4 v0 = src[2 * off + 0], v1 = src[2 * off + 1];
        float4 v2 = src[2 * off + 2], v3 = src[2 * off + 3];
        uint4 o0, o1;
        __nv_bfloat162 t;
        t = __floats2bfloat162_rn(v0.x, v0.y); o0.x = *(uint32_t*)&t;
        t = __floats2bfloat162_rn(v0.z, v0.w); o0.y = *(uint32_t*)&t;
        t = __floats2bfloat162_rn(v1.x, v1.y); o0.z = *(uint32_t*)&t;
        t = __floats2bfloat162_rn(v1.z, v1.w); o0.w = *(uint32_t*)&t;
        t = __floats2bfloat162_rn(v2.x, v2.y); o1.x = *(uint32_t*)&t;
        t = __floats2bfloat162_rn(v2.z, v2.w); o1.y = *(uint32_t*)&t;
        t = __floats2bfloat162_rn(v3.x, v3.y); o1.z = *(uint32_t*)&t;
        t = __floats2bfloat162_rn(v3.z, v3.w); o1.w = *(uint32_t*)&t;
        dst[off + 0] = o0;
        dst[off + 1] = o1;
    }
}

// ---------------------------------------------------------------------------
// P = elu(X @ Wt.T + cvec). bf16 inputs, cp.async 3-stage pipeline,
// copy-before-MMA ordering. 256 threads = 8 warps (2x4, 64x32/warp), 2 CTAs/SM.
__global__ __launch_bounds__(256, 2)
void k_proj_mma() {
    extern __shared__ char dynsm[];
    const uint32_t sb = smem_u32(dynsm);

    const int which = blockIdx.z;
    const __nv_bfloat16* __restrict__ X  = which ? g_x2  : g_x1;
    const __nv_bfloat16* __restrict__ Wt = which ? g_wt2 : g_wt1;
    __nv_bfloat16* __restrict__ P = which ? g_p2 : g_p1;
    const float* __restrict__ cvec = g_cvec + which * KDIM;
    float* __restrict__ scol = g_s + which * KDIM;

    const int tid  = threadIdx.x;
    const int wid  = tid >> 5;
    const int lane = tid & 31;
    const int warpRow = wid & 1;
    const int warpCol = wid >> 1;
    const int rowBase = blockIdx.y * BM;
    const int colBase = blockIdx.x * BN;

    const int cprow = tid >> 3;
    const int cpcol = tid & 7;
    const uint32_t cpswz = (uint32_t)((cpcol ^ (cprow & 7)) << 4);
    const __nv_bfloat16* gA = X  + (size_t)(rowBase + cprow) * KDIM + cpcol * 8;
    const __nv_bfloat16* gB = Wt + (size_t)(colBase + cprow) * KDIM + cpcol * 8;

    const int laneQ = lane & 7;
    const int blkId = lane >> 3;
    const uint32_t aKc0 = (uint32_t)(blkId >> 1);
    const uint32_t bKc0 = (uint32_t)(blkId & 1);
    uint32_t aRowOff[4], bRowOff[2];
#pragma unroll
    for (int rb = 0; rb < 4; ++rb)
        aRowOff[rb] = (uint32_t)(warpRow * 64 + rb * 16 + (blkId & 1) * 8 + laneQ) * 128u;
#pragma unroll
    for (int pr = 0; pr < 2; ++pr)
        bRowOff[pr] = (uint32_t)(warpCol * 32 + pr * 16 + (blkId >> 1) * 8 + laneQ) * 128u;

    uint32_t aSwT[4], bSwT[4];
#pragma unroll
    for (int ks = 0; ks < 4; ++ks) {
        aSwT[ks] = (uint32_t)((((uint32_t)(ks * 2) + aKc0) ^ (uint32_t)laneQ) << 4);
        bSwT[ks] = (uint32_t)((((uint32_t)(ks * 2) + bKc0) ^ (uint32_t)laneQ) << 4);
    }

    float acc[4][4][4] = {};

    auto issue = [&](int s, int c) {
        const uint32_t stg = sb + (uint32_t)s * STAGE_B;
        const int ko = c * KC;
#pragma unroll
        for (int it = 0; it < 4; ++it) {
            uint32_t soff = (uint32_t)(cprow + 32 * it) * 128u + cpswz;
            cp16(stg + soff,          gA + (size_t)(32 * it) * KDIM + ko);
            cp16(stg + TILE_B + soff, gB + (size_t)(32 * it) * KDIM + ko);
        }
        cp_commit();
    };

    issue(0, 0);
    issue(1, 1);

    int stage = 0;
    int wstage = 2;
    for (int c = 0; c < NCHUNK; ++c) {
        if (c == NCHUNK - 1) cp_wait<0>(); else cp_wait<1>();
        __syncthreads();

        if (c + 2 < NCHUNK) {
            issue(wstage, c + 2);
            wstage = (wstage == 2) ? 0 : wstage + 1;
        }

        const uint32_t smA = sb + (uint32_t)stage * STAGE_B;
        const uint32_t smB = smA + TILE_B;
#pragma unroll
        for (int ks = 0; ks < 4; ++ks) {
            uint32_t af[4][4], bf[2][4];
#pragma unroll
            for (int rb = 0; rb < 4; ++rb)
                ldsm_x4(smA + aRowOff[rb] + aSwT[ks], af[rb]);
#pragma unroll
            for (int pr = 0; pr < 2; ++pr)
                ldsm_x4(smB + bRowOff[pr] + bSwT[ks], bf[pr]);
#pragma unroll
            for (int cf = 0; cf < 4; ++cf) {
                const uint32_t* bp = &bf[cf >> 1][(cf & 1) * 2];
#pragma unroll
                for (int rb = 0; rb < 4; ++rb)
                    mma16816(acc[rb][cf], af[rb], bp);
            }
        }

        stage = (stage == 2) ? 0 : stage + 1;
    }

    // ---- epilogue: +cvec, ELU, bf16 store, column sums ----
    const int gq  = lane >> 2;
    const int tig = lane & 3;
    float csum[8];
#pragma unroll
    for (int j = 0; j < 8; ++j) csum[j] = 0.f;

#pragma unroll
    for (int rb = 0; rb < 4; ++rb) {
#pragma unroll
        for (int cf = 0; cf < 4; ++cf) {
            const int col = colBase + warpCol * 32 + cf * 8 + tig * 2;
            const float cv0 = cvec[col], cv1 = cvec[col + 1];
#pragma unroll
            for (int half = 0; half < 2; ++half) {
                const int row = rowBase + warpRow * 64 + rb * 16 + gq + half * 8;
                float v0 = acc[rb][cf][half * 2 + 0] + cv0;
                float v1 = acc[rb][cf][half * 2 + 1] + cv1;
                v0 = (v0 > 0.f) ? v0 : expm1f(v0);
                v1 = (v1 > 0.f) ? v1 : expm1f(v1);
                __nv_bfloat162 pk = __floats2bfloat162_rn(v0, v1);
                *(__nv_bfloat162*)(P + (size_t)row * KDIM + col) = pk;
                csum[cf * 2 + 0] += v0;
                csum[cf * 2 + 1] += v1;
            }
        }
    }
#pragma unroll
    for (int j = 0; j < 8; ++j) {
        float v = csum[j];
        v += __shfl_xor_sync(0xffffffffu, v, 4);
        v += __shfl_xor_sync(0xffffffffu, v, 8);
        v += __shfl_xor_sync(0xffffffffu, v, 16);
        if (gq == 0) {
            int col = colBase + warpCol * 32 + (j >> 1) * 8 + tig * 2 + (j & 1);
            atomicAdd(&scol[col], v);
        }
    }
}

// ---------------------------------------------------------------------------
// logits: 2 rows per warp. Also merges block max into g_mx[z].
__global__ void k_matvec(int M) {
    __shared__ float smax[8];
    const int gw   = (blockIdx.x * blockDim.x + threadIdx.x) >> 5;
    const int wloc = threadIdx.x >> 5;
    const int lane = threadIdx.x & 31;
    const int z = blockIdx.y;
    const int r0 = gw * 2;
    const __nv_bfloat16* P = z ? g_p2 : g_p1;
    const uint4* pr0 = (const uint4*)(P + (size_t)r0 * KDIM);
    const uint4* pr1 = (const uint4*)(P + (size_t)(r0 + 1) * KDIM);
    const float4* s4 = (const float4*)(g_s + (1 - z) * KDIM);
    float sum0 = 0.f, sum1 = 0.f;
#pragma unroll
    for (int it = 0; it < KDIM / 256; ++it) {
        uint4 pa = pr0[lane + it * 32];
        uint4 pb = pr1[lane + it * 32];
        float4 sa = s4[(lane + it * 32) * 2 + 0];
        float4 sbv = s4[(lane + it * 32) * 2 + 1];
        float2 q;
        q = __bfloat1622float2(*(const __nv_bfloat162*)&pa.x); sum0 += q.x * sa.x + q.y * sa.y;
        q = __bfloat1622float2(*(const __nv_bfloat162*)&pa.y); sum0 += q.x * sa.z + q.y * sa.w;
        q = __bfloat1622float2(*(const __nv_bfloat162*)&pa.z); sum0 += q.x * sbv.x + q.y * sbv.y;
        q = __bfloat1622float2(*(const __nv_bfloat162*)&pa.w); sum0 += q.x * sbv.z + q.y * sbv.w;
        q = __bfloat1622float2(*(const __nv_bfloat162*)&pb.x); sum1 += q.x * sa.x + q.y * sa.y;
        q = __bfloat1622float2(*(const __nv_bfloat162*)&pb.y); sum1 += q.x * sa.z + q.y * sa.w;
        q = __bfloat1622float2(*(const __nv_bfloat162*)&pb.z); sum1 += q.x * sbv.x + q.y * sbv.y;
        q = __bfloat1622float2(*(const __nv_bfloat162*)&pb.w); sum1 += q.x * sbv.z + q.y * sbv.w;
    }
#pragma unroll
    for (int o = 16; o; o >>= 1) {
        sum0 += __shfl_xor_sync(0xffffffffu, sum0, o);
        sum1 += __shfl_xor_sync(0xffffffffu, sum1, o);
    }
    if (lane == 0) {
        g_logits[z * A_MAX + r0]     = sum0;
        g_logits[z * A_MAX + r0 + 1] = sum1;
        smax[wloc] = fmaxf(sum0, sum1);
    }
    __syncthreads();
    if (threadIdx.x == 0) {
        float m = smax[0];
#pragma unroll
        for (int i = 1; i < 8; ++i) m = fmaxf(m, smax[i]);
        atomicMax(&g_mx[z], fkey(m));
    }
}

// out[z*KDIM + col4] += sum_r e^{l_r - mx} * seq_z[r, col4] (UNNORMALIZED);
// RPB=32 (grid 512, same as R12), row loop in explicit batches of 8 float4
// loads to force register-resident front-batching (MLP ~8).
__global__ void k_pool(const float* __restrict__ seq1, const float* __restrict__ seq2,
                       float* __restrict__ out) {
    __shared__ float wsh[RPB];
    const int z = blockIdx.z;
    const float* seq = z ? seq2 : seq1;
    const int c4 = threadIdx.x;
    const int r0 = blockIdx.y * RPB;
    if (threadIdx.x < 32) {
        float mx = fkey_inv(g_mx[z]);
        float e = expf(g_logits[z * A_MAX + r0 + threadIdx.x] - mx);
        wsh[threadIdx.x] = e;
        float t = e;
#pragma unroll
        for (int o = 16; o; o >>= 1) t += __shfl_xor_sync(0xffffffffu, t, o);
        if (threadIdx.x == 0) atomicAdd(&g_sum[z], t);
    }
    __syncthreads();
    const float* base = seq + (size_t)r0 * KDIM + c4 * 4;
    float4 acc = {0.f, 0.f, 0.f, 0.f};
#pragma unroll
    for (int rb = 0; rb < RPB; rb += 8) {
        float4 v[8];
#pragma unroll
        for (int j = 0; j < 8; ++j)
            v[j] = *(const float4*)(base + (size_t)(rb + j) * KDIM);
#pragma unroll
        for (int j = 0; j < 8; ++j) {
            float wr = wsh[rb + j];
            acc.x += wr * v[j].x; acc.y += wr * v[j].y;
            acc.z += wr * v[j].z; acc.w += wr * v[j].w;
        }
    }
    float* o = out + z * KDIM + c4 * 4;
    atomicAdd(o + 0, acc.x);
    atomicAdd(o + 1, acc.y);
    atomicAdd(o + 2, acc.z);
    atomicAdd(o + 3, acc.w);
}

// out[i] /= g_sum[z]  (2048 elems)
__global__ void k_norm(float* __restrict__ out) {
    int i = blockIdx.x * blockDim.x + threadIdx.x;
    if (i < 2 * KDIM) out[i] *= (1.f / g_sum[i >> 10]);
}

// ---------------------------------------------------------------------------
extern "C" void kernel_launch(void* const* d_in, const int* in_sizes, int n_in,
                              void* d_out, int out_size) {
    const float* seq1 = (const float*)d_in[0];
    const float* seq2 = (const float*)d_in[1];
    const float* ctx  = (const float*)d_in[2];
    const float* Wc1  = (const float*)d_in[3];
    const float* W1   = (const float*)d_in[4];
    const float* b1   = (const float*)d_in[5];
    const float* Wc2  = (const float*)d_in[6];
    const float* W2   = (const float*)d_in[7];
    const float* b2   = (const float*)d_in[8];
    float* out = (float*)d_out;

    const int a = in_sizes[0] / KDIM;   // 8192
    const int b = in_sizes[1] / KDIM;   // 8192

    cudaFuncSetAttribute(k_proj_mma, cudaFuncAttributeMaxDynamicSharedMemorySize, SMEM_DYN);

    k_prep<<<CVEC_BLOCKS + CONV_BLOCKS, 256>>>(
        (const float4*)seq1, (const float4*)seq2, (const float4*)W1, (const float4*)W2,
        Wc1, Wc2, b1, b2, ctx, out, out_size);

    {
        dim3 g(KDIM / BN, a / BM, 2);
        k_proj_mma<<<g, 256, SMEM_DYN>>>();
    }

    {
        dim3 gm(a / 16, 2);
        k_matvec<<<gm, 256>>>(a);
    }

    {
        dim3 gp(1, a / RPB, 2);
        k_pool<<<gp, 256>>>(seq1, seq2, out);
    }

    k_norm<<<8, 256>>>(out);
}